// round 5
// baseline (speedup 1.0000x reference)
#include <cuda_runtime.h>
#include <cstdint>
#include <cstddef>

#define NN 50000
#define EE 800000
#define HID 128
#define EDIM 32
#define XS 132   // transposed-X row stride (floats); k*XS*4 % 16 == 0 -> LDS.128 ok

// ---------------- scratch (static __device__ — allocation-free) ----------------
__device__ __align__(16) float g_x0[(size_t)NN * HID];
__device__ __align__(16) float g_x1[(size_t)NN * HID];
__device__ __align__(16) float g_mx[(size_t)NN * HID];
__device__ __align__(16) float g_me[(size_t)NN * HID];
__device__ __align__(16) float g_scores[NN];
__device__ int g_src[EE];
__device__ int g_dst[EE];
__device__ unsigned g_maxbits;
__device__ float g_sum;

// ---------------- helpers ----------------
__device__ __forceinline__ void red_add_v4(float* addr, float4 v) {
    asm volatile("red.global.add.v4.f32 [%0], {%1,%2,%3,%4};"
                 :: "l"(addr), "f"(v.x), "f"(v.y), "f"(v.z), "f"(v.w)
                 : "memory");
}

// packed f32x2 FMA: d = a*b + c (two fp32 lanes per instruction)
__device__ __forceinline__ unsigned long long fma2(unsigned long long a,
                                                   unsigned long long b,
                                                   unsigned long long c) {
    unsigned long long d;
    asm("fma.rn.f32x2 %0, %1, %2, %3;" : "=l"(d) : "l"(a), "l"(b), "l"(c));
    return d;
}
__device__ __forceinline__ unsigned long long dup2(float s) {
    unsigned long long d;
    asm("mov.b64 %0, {%1, %1};" : "=l"(d) : "f"(s));
    return d;
}
__device__ __forceinline__ void unpack2(unsigned long long v, float& lo, float& hi) {
    asm("mov.b64 {%0, %1}, %2;" : "=f"(lo), "=f"(hi) : "l"(v));
}

__device__ __forceinline__ unsigned enc_ordered(float f) {
    unsigned b = __float_as_uint(f);
    return (b & 0x80000000u) ? ~b : (b | 0x80000000u);
}
__device__ __forceinline__ float dec_ordered(unsigned u) {
    unsigned b = (u & 0x80000000u) ? (u ^ 0x80000000u) : ~u;
    return __uint_as_float(b);
}

// ---------------- edge index normalization (int64 OR int32 input) ----------------
__global__ void convert_edges(const void* __restrict__ ei) {
    __shared__ int is64;
    if (threadIdx.x == 0) {
        const int* p = (const int*)ei;
        int z = 0;
        #pragma unroll
        for (int i = 0; i < 64; i++) z |= p[2 * i + 1];
        is64 = (z == 0);
    }
    __syncthreads();
    const int idx = blockIdx.x * blockDim.x + threadIdx.x;
    const int stride = gridDim.x * blockDim.x;
    if (is64) {
        const long long* p = (const long long*)ei;
        for (int e = idx; e < EE; e += stride) {
            g_src[e] = (int)p[e];
            g_dst[e] = (int)p[EE + e];
        }
    } else {
        const int* p = (const int*)ei;
        for (int e = idx; e < EE; e += stride) {
            g_src[e] = p[e];
            g_dst[e] = p[EE + e];
        }
    }
}

// ---------------- zero kernels ----------------
__global__ void zero_main() {
    const int n4 = NN * HID / 4;
    float4* a = (float4*)g_me;
    float4* b = (float4*)g_mx;
    const float4 z = make_float4(0.f, 0.f, 0.f, 0.f);
    for (int i = blockIdx.x * blockDim.x + threadIdx.x; i < n4;
         i += gridDim.x * blockDim.x) {
        a[i] = z;
        b[i] = z;
    }
    if (blockIdx.x == 0 && threadIdx.x == 0) { g_maxbits = 0u; g_sum = 0.f; }
}

__global__ void zero_mx() {
    const int n4 = NN * HID / 4;
    float4* b = (float4*)g_mx;
    const float4 z = make_float4(0.f, 0.f, 0.f, 0.f);
    for (int i = blockIdx.x * blockDim.x + threadIdx.x; i < n4;
         i += gridDim.x * blockDim.x)
        b[i] = z;
}

// ---------------- f32x2 row-projection GEMM: out = relu(in @ W + b) ----------------
// Block = 256 threads = 8 warps. Tile = 128 rows x 128 cols.
// Warp w owns rows [w*16, w*16+16) as 8 row-PAIRS; lane owns cols [lane*4,+4).
// X staged transposed (X_s[k*XS + row]); W staged in 128-k chunks (two phases
// for K=256 to fit 228KB smem). Per warp-k: 1 LDS.128 W + 4 bcast LDS.128 X
// + 4 dup movs + 32 FMA2 (=64 FMAs) -> fma-pipe bound.
template <int K, bool CONCAT>
__global__ void proj_kernel(const float* __restrict__ in0,
                            const float* __restrict__ in1,
                            const float* __restrict__ W,
                            const float* __restrict__ bias,
                            float* __restrict__ out, int rows) {
    extern __shared__ float sh[];
    float* W_s = sh;             // 128*128 floats (one K-chunk)
    float* X_s = sh + 128 * 128; // K*XS floats (transposed, full K)
    const int tid = threadIdx.x;
    const int tile0 = blockIdx.x * 128;

    {   // stage all 128 rows transposed (consecutive tid -> consecutive r: conflict-free STS)
        const int KC = K / 4;
        for (int i = tid; i < 128 * KC; i += 256) {
            const int r = i & 127, kc = i >> 7;
            const int g = tile0 + r;
            float4 v = make_float4(0.f, 0.f, 0.f, 0.f);
            if (g < rows) {
                if (CONCAT) {
                    v = (kc < 32) ? ((const float4*)(in0 + (size_t)g * 128))[kc]
                                  : ((const float4*)(in1 + (size_t)g * 128))[kc - 32];
                } else {
                    v = ((const float4*)(in0 + (size_t)g * K))[kc];
                }
            }
            float* xp = &X_s[(kc * 4) * XS + r];
            xp[0 * XS] = v.x;
            xp[1 * XS] = v.y;
            xp[2 * XS] = v.z;
            xp[3 * XS] = v.w;
        }
    }

    const int lane = tid & 31;
    const int w = tid >> 5;
    const int rb = w * 16;
    const float4 bias4 = ((const float4*)bias)[lane];
    unsigned long long acc[8][4];
    {
        const unsigned long long b0 = dup2(bias4.x), b1 = dup2(bias4.y);
        const unsigned long long b2 = dup2(bias4.z), b3 = dup2(bias4.w);
        #pragma unroll
        for (int p = 0; p < 8; p++) {
            acc[p][0] = b0; acc[p][1] = b1; acc[p][2] = b2; acc[p][3] = b3;
        }
    }

    #pragma unroll
    for (int ph = 0; ph < K / 128; ph++) {
        __syncthreads();   // all warps done with previous W chunk (and X staged at ph=0)
        {   // stage W chunk ph: rows [ph*128, ph*128+128) of W (K x 128)
            const float4* Wg = (const float4*)(W + (size_t)ph * 128 * 128);
            float4* Ws4 = (float4*)W_s;
            for (int i = tid; i < 128 * 32; i += 256) Ws4[i] = Wg[i];
        }
        __syncthreads();

        const float* Xph = &X_s[(size_t)ph * 128 * XS];
        #pragma unroll 4
        for (int k = 0; k < 128; k++) {
            const float4 wv = ((const float4*)&W_s[k * 128])[lane];
            const unsigned long long w0 = dup2(wv.x), w1 = dup2(wv.y);
            const unsigned long long w2 = dup2(wv.z), w3 = dup2(wv.w);
            const float* xb = &Xph[k * XS + rb];
            const ulonglong2 xa = *(const ulonglong2*)(xb + 0);
            const ulonglong2 xc = *(const ulonglong2*)(xb + 4);
            const ulonglong2 xd = *(const ulonglong2*)(xb + 8);
            const ulonglong2 xe = *(const ulonglong2*)(xb + 12);
            const unsigned long long xp[8] = {xa.x, xa.y, xc.x, xc.y,
                                              xd.x, xd.y, xe.x, xe.y};
            #pragma unroll
            for (int p = 0; p < 8; p++) {
                acc[p][0] = fma2(xp[p], w0, acc[p][0]);
                acc[p][1] = fma2(xp[p], w1, acc[p][1]);
                acc[p][2] = fma2(xp[p], w2, acc[p][2]);
                acc[p][3] = fma2(xp[p], w3, acc[p][3]);
            }
        }
    }

    #pragma unroll
    for (int p = 0; p < 8; p++) {
        float4 v0, v1;
        unpack2(acc[p][0], v0.x, v1.x);
        unpack2(acc[p][1], v0.y, v1.y);
        unpack2(acc[p][2], v0.z, v1.z);
        unpack2(acc[p][3], v0.w, v1.w);
        const int g0 = tile0 + rb + 2 * p;
        if (g0 < rows) {
            v0.x = fmaxf(v0.x, 0.f); v0.y = fmaxf(v0.y, 0.f);
            v0.z = fmaxf(v0.z, 0.f); v0.w = fmaxf(v0.w, 0.f);
            ((float4*)(out + (size_t)g0 * 128))[lane] = v0;
        }
        if (g0 + 1 < rows) {
            v1.x = fmaxf(v1.x, 0.f); v1.y = fmaxf(v1.y, 0.f);
            v1.z = fmaxf(v1.z, 0.f); v1.w = fmaxf(v1.w, 0.f);
            ((float4*)(out + (size_t)(g0 + 1) * 128))[lane] = v1;
        }
    }
}

// ---------------- fused edge projection + segment-sum into m_e (f32x2) ----------------
// m_e[dst[e]] += relu(EF[e] @ We + be). Tile = 128 edges; EE % 128 == 0.
__global__ void edge_proj_kernel(const float* __restrict__ EF,
                                 const float* __restrict__ W,
                                 const float* __restrict__ bias) {
    __shared__ __align__(16) float W_s[EDIM * 128];   // 16 KB
    __shared__ __align__(16) float X_s[EDIM * XS];    // ~16.9 KB, transposed
    __shared__ int dst_s[128];
    const int tid = threadIdx.x;
    const int tile0 = blockIdx.x * 128;

    for (int i = tid; i < EDIM * 128 / 4; i += 256)
        ((float4*)W_s)[i] = ((const float4*)W)[i];

    {   // transpose-stage 128 edge rows (KC = 8)
        for (int i = tid; i < 128 * (EDIM / 4); i += 256) {
            const int r = i & 127, kc = i >> 7;
            const float4 v = ((const float4*)(EF + (size_t)(tile0 + r) * EDIM))[kc];
            float* xp = &X_s[(kc * 4) * XS + r];
            xp[0 * XS] = v.x;
            xp[1 * XS] = v.y;
            xp[2 * XS] = v.z;
            xp[3 * XS] = v.w;
        }
    }
    if (tid < 128) dst_s[tid] = g_dst[tile0 + tid];
    __syncthreads();

    const int lane = tid & 31;
    const int w = tid >> 5;
    const int rb = w * 16;
    const float4 bias4 = ((const float4*)bias)[lane];
    unsigned long long acc[8][4];
    {
        const unsigned long long b0 = dup2(bias4.x), b1 = dup2(bias4.y);
        const unsigned long long b2 = dup2(bias4.z), b3 = dup2(bias4.w);
        #pragma unroll
        for (int p = 0; p < 8; p++) {
            acc[p][0] = b0; acc[p][1] = b1; acc[p][2] = b2; acc[p][3] = b3;
        }
    }

    #pragma unroll
    for (int k = 0; k < EDIM; k++) {
        const float4 wv = ((const float4*)&W_s[k * 128])[lane];
        const unsigned long long w0 = dup2(wv.x), w1 = dup2(wv.y);
        const unsigned long long w2 = dup2(wv.z), w3 = dup2(wv.w);
        const float* xb = &X_s[k * XS + rb];
        const ulonglong2 xa = *(const ulonglong2*)(xb + 0);
        const ulonglong2 xc = *(const ulonglong2*)(xb + 4);
        const ulonglong2 xd = *(const ulonglong2*)(xb + 8);
        const ulonglong2 xe = *(const ulonglong2*)(xb + 12);
        const unsigned long long xp[8] = {xa.x, xa.y, xc.x, xc.y,
                                          xd.x, xd.y, xe.x, xe.y};
        #pragma unroll
        for (int p = 0; p < 8; p++) {
            acc[p][0] = fma2(xp[p], w0, acc[p][0]);
            acc[p][1] = fma2(xp[p], w1, acc[p][1]);
            acc[p][2] = fma2(xp[p], w2, acc[p][2]);
            acc[p][3] = fma2(xp[p], w3, acc[p][3]);
        }
    }

    #pragma unroll
    for (int p = 0; p < 8; p++) {
        float4 v0, v1;
        unpack2(acc[p][0], v0.x, v1.x);
        unpack2(acc[p][1], v0.y, v1.y);
        unpack2(acc[p][2], v0.z, v1.z);
        unpack2(acc[p][3], v0.w, v1.w);
        v0.x = fmaxf(v0.x, 0.f); v0.y = fmaxf(v0.y, 0.f);
        v0.z = fmaxf(v0.z, 0.f); v0.w = fmaxf(v0.w, 0.f);
        v1.x = fmaxf(v1.x, 0.f); v1.y = fmaxf(v1.y, 0.f);
        v1.z = fmaxf(v1.z, 0.f); v1.w = fmaxf(v1.w, 0.f);
        const int r0 = rb + 2 * p;
        red_add_v4(&g_me[(size_t)dst_s[r0] * 128 + lane * 4], v0);
        red_add_v4(&g_me[(size_t)dst_s[r0 + 1] * 128 + lane * 4], v1);
    }
}

// ---------------- m_x[dst] += x[src] (warp per edge, v4 atomics) ----------------
__global__ void gather_scatter(const float* __restrict__ x) {
    const int lane = threadIdx.x & 31;
    const int warp = (blockIdx.x * blockDim.x + threadIdx.x) >> 5;
    const int nwarps = (gridDim.x * blockDim.x) >> 5;
    for (int e = warp; e < EE; e += nwarps) {
        const int s = g_src[e];
        const int d = g_dst[e];
        const float4 v = ((const float4*)(x + (size_t)s * 128))[lane];
        red_add_v4(&g_mx[(size_t)d * 128 + lane * 4], v);
    }
}

// ---------------- scores + global max ----------------
__global__ void scores_kernel(const float* __restrict__ x,
                              const float* __restrict__ Wo,
                              const float* __restrict__ bo) {
    const int lane = threadIdx.x & 31;
    const int w = threadIdx.x >> 5;
    const int nw = blockDim.x >> 5;
    const float4 wv = ((const float4*)Wo)[lane];
    const float b = *bo;
    float lmax = -3.402823466e38f;
    for (int n = blockIdx.x * nw + w; n < NN; n += gridDim.x * nw) {
        const float4 xv = ((const float4*)(x + (size_t)n * 128))[lane];
        float d = xv.x * wv.x + xv.y * wv.y + xv.z * wv.z + xv.w * wv.w;
        #pragma unroll
        for (int o = 16; o; o >>= 1) d += __shfl_down_sync(0xffffffffu, d, o);
        if (lane == 0) {
            const float sc = d + b;
            g_scores[n] = sc;
            if (sc > lmax) lmax = sc;
        }
    }
    __shared__ float sm[8];
    lmax = __shfl_sync(0xffffffffu, lmax, 0);
    if (lane == 0) sm[w] = lmax;
    __syncthreads();
    if (threadIdx.x == 0) {
        float m = sm[0];
        for (int i = 1; i < nw; i++) m = fmaxf(m, sm[i]);
        atomicMax(&g_maxbits, enc_ordered(m));
    }
}

// ---------------- sum of exp ----------------
__global__ void sum_kernel() {
    const float maxf = dec_ordered(g_maxbits);
    float s = 0.f;
    for (int n = blockIdx.x * blockDim.x + threadIdx.x; n < NN;
         n += gridDim.x * blockDim.x)
        s += expf(g_scores[n] - maxf);
    #pragma unroll
    for (int o = 16; o; o >>= 1) s += __shfl_down_sync(0xffffffffu, s, o);
    __shared__ float sm[8];
    const int lane = threadIdx.x & 31, w = threadIdx.x >> 5;
    if (lane == 0) sm[w] = s;
    __syncthreads();
    if (threadIdx.x == 0) {
        float t = 0.f;
        const int nw = blockDim.x >> 5;
        for (int i = 0; i < nw; i++) t += sm[i];
        atomicAdd(&g_sum, t);
    }
}

// ---------------- normalize ----------------
__global__ void finalize_kernel(float* __restrict__ out) {
    const float maxf = dec_ordered(g_maxbits);
    const float inv = 1.0f / g_sum;
    const int n = blockIdx.x * blockDim.x + threadIdx.x;
    if (n < NN) out[n] = expf(g_scores[n] - maxf) * inv;
}

// ---------------- launch ----------------
extern "C" void kernel_launch(void* const* d_in, const int* in_sizes, int n_in,
                              void* d_out, int out_size) {
    const float* NF = (const float*)d_in[0];
    const float* EF = (const float*)d_in[1];
    const float* Wn = (const float*)d_in[2];
    const float* bn = (const float*)d_in[3];
    const float* We = (const float*)d_in[4];
    const float* be = (const float*)d_in[5];
    const float* W1 = (const float*)d_in[6];
    const float* b1 = (const float*)d_in[7];
    const float* W2 = (const float*)d_in[8];
    const float* b2 = (const float*)d_in[9];
    const float* Wo = (const float*)d_in[10];
    const float* bo = (const float*)d_in[11];
    const void*  EI = d_in[12];
    float* out = (float*)d_out;

    float *px0, *px1, *pmx, *pme;
    cudaGetSymbolAddress((void**)&px0, g_x0);
    cudaGetSymbolAddress((void**)&px1, g_x1);
    cudaGetSymbolAddress((void**)&pmx, g_mx);
    cudaGetSymbolAddress((void**)&pme, g_me);

    const int SMEM_128 = (128 * 128 + 128 * XS) * 4;   // ~130 KB
    const int SMEM_256 = (128 * 128 + 256 * XS) * 4;   // ~196 KB (W chunked)
    cudaFuncSetAttribute(proj_kernel<128, false>,
                         cudaFuncAttributeMaxDynamicSharedMemorySize, SMEM_128);
    cudaFuncSetAttribute(proj_kernel<256, true>,
                         cudaFuncAttributeMaxDynamicSharedMemorySize, SMEM_256);

    const int nTilesN = (NN + 127) / 128;   // 391
    const int nTilesE = EE / 128;           // 6250

    // normalize edge indices (int64/int32 agnostic)
    convert_edges<<<512, 256>>>(EI);
    // zero m_e, m_x, scalars
    zero_main<<<2048, 256>>>();
    // x0 = relu(NF @ Wn + bn)
    proj_kernel<128, false><<<nTilesN, 256, SMEM_128>>>(NF, nullptr, Wn, bn, px0, NN);
    // m_e = segment_sum(relu(EF @ We + be), dst)   [computed once, reused by both layers]
    edge_proj_kernel<<<nTilesE, 256>>>(EF, We, be);
    // layer 1
    gather_scatter<<<1184, 256>>>(px0);
    proj_kernel<256, true><<<nTilesN, 256, SMEM_256>>>(pmx, pme, W1, b1, px1, NN);
    // layer 2
    zero_mx<<<2048, 256>>>();
    gather_scatter<<<1184, 256>>>(px1);
    proj_kernel<256, true><<<nTilesN, 256, SMEM_256>>>(pmx, pme, W2, b2, px0, NN);
    // scores + softmax
    scores_kernel<<<512, 128>>>(px0, Wo, bo);
    sum_kernel<<<512, 256>>>();
    finalize_kernel<<<(NN + 255) / 256, 256>>>(out);
}